// round 16
// baseline (speedup 1.0000x reference)
#include <cuda_runtime.h>
#include <cuda_fp16.h>
#include <cstdint>

#define Bn 4
#define Cc 256
#define Nn 1024
#define Hh 8
#define Dd 256
#define HD 2048   // H*D
#define CEXP 5.0f // fixed softmax shift

// Scratch (device globals; no allocation allowed)
__device__ __half g_Xh[(size_t)Bn * Cc * Nn];        // x fp16 [b][c][n]
__device__ __half g_Yh[(size_t)Bn * Cc * Nn];        // y fp16
__device__ __half g_Wqh[HD * Cc];
__device__ __half g_Wkh[HD * Cc];
__device__ __half g_Wvh[HD * Cc];
__device__ __half g_Wph[Cc * Cc];
__device__ __half g_Qh[(size_t)Bn * HD * Nn];        // [bh][d][n]
__device__ __half g_Kh[(size_t)Bn * HD * Nn];        // [bh][d][n]
__device__ __half g_Vh[(size_t)Bn * HD * Nn];        // [bh][d][n]
__device__ float  g_YP[(size_t)Bn * Cc * Nn];        // [b][d][n] fp32
__device__ __half g_Sh[(size_t)Bn * Hh * Nn * Nn];   // [bh][i][j] P' = exp(s - C)
__device__ float  g_Lp[(size_t)Bn * Hh * Nn * 8];    // per-(row, j-tile) partial sums

// ---------------------------------------------------------------------------
__device__ __forceinline__ uint32_t smem_u32(const void* p) {
    uint32_t a;
    asm("{ .reg .u64 t; cvta.to.shared.u64 t, %1; cvt.u32.u64 %0, t; }" : "=r"(a) : "l"(p));
    return a;
}
__device__ __forceinline__ unsigned h2u(float a, float b) {
    __half2 h = __floats2half2_rn(a, b);
    return *reinterpret_cast<unsigned*>(&h);
}
__device__ __forceinline__ void mma16(float* c, const unsigned* a, const unsigned* b) {
    asm volatile(
        "mma.sync.aligned.m16n8k16.row.col.f32.f16.f16.f32 "
        "{%0,%1,%2,%3},{%4,%5,%6,%7},{%8,%9},{%0,%1,%2,%3};\n"
        : "+f"(c[0]), "+f"(c[1]), "+f"(c[2]), "+f"(c[3])
        : "r"(a[0]), "r"(a[1]), "r"(a[2]), "r"(a[3]), "r"(b[0]), "r"(b[1]));
}
__device__ __forceinline__ void ldm4t(unsigned* r, uint32_t addr) {
    asm volatile("ldmatrix.sync.aligned.m8n8.x4.trans.shared.b16 {%0,%1,%2,%3}, [%4];"
                 : "=r"(r[0]), "=r"(r[1]), "=r"(r[2]), "=r"(r[3]) : "r"(addr));
}
__device__ __forceinline__ void ldm4(unsigned* r, uint32_t addr) {
    asm volatile("ldmatrix.sync.aligned.m8n8.x4.shared.b16 {%0,%1,%2,%3}, [%4];"
                 : "=r"(r[0]), "=r"(r[1]), "=r"(r[2]), "=r"(r[3]) : "r"(addr));
}
__device__ __forceinline__ void cp16(uint32_t s, const void* g) {
    asm volatile("cp.async.ca.shared.global [%0], [%1], 16;" :: "r"(s), "l"(g) : "memory");
}
#define CP_COMMIT() asm volatile("cp.async.commit_group;" ::: "memory")
#define CP_WAIT1()  asm volatile("cp.async.wait_group 1;" ::: "memory")

// Tile geometry: Ktile=64, 3 stages.
#define SWZ_SZ 16384
#define PAD_SZ 18432

__device__ __forceinline__ void stage_kn(uint32_t sb, const __half* g, int ldn, int t) {
#pragma unroll
    for (int i = 0; i < 4; i++) {
        int id = t + i * 256;
        int kr = id >> 4, c = id & 15;
        cp16(sb + kr * 256 + ((c ^ (kr & 7)) << 4), g + (size_t)kr * ldn + c * 8);
    }
}
__device__ __forceinline__ void stage_mk(uint32_t sb, const __half* g, int ldk, int t) {
#pragma unroll
    for (int i = 0; i < 4; i++) {
        int id = t + i * 256;
        int r = id >> 3, c = id & 7;
        cp16(sb + r * 144 + c * 16, g + (size_t)r * ldk + c * 8);
    }
}

// ===========================================================================
// fp32 -> fp16 conversion, one group of 3 arrays per launch.
// grp 0: {x, Wq, Wk}; grp 1: {y, Wv, Wp}. blockIdx.y = segment.
// ===========================================================================
__global__ void __launch_bounds__(256) f2h_grp(const float* __restrict__ a,
                                               const float* __restrict__ b,
                                               const float* __restrict__ c,
                                               int grp) {
    const int seg = blockIdx.y;
    const float* in;
    __half* out;
    int n4;
    if (grp == 0) {
        if (seg == 0)      { in = a; out = g_Xh;  n4 = Bn * Cc * Nn / 4; }
        else if (seg == 1) { in = b; out = g_Wqh; n4 = HD * Cc / 4; }
        else               { in = c; out = g_Wkh; n4 = HD * Cc / 4; }
    } else {
        if (seg == 0)      { in = a; out = g_Yh;  n4 = Bn * Cc * Nn / 4; }
        else if (seg == 1) { in = b; out = g_Wvh; n4 = HD * Cc / 4; }
        else               { in = c; out = g_Wph; n4 = Cc * Cc / 4; }
    }
    int i = blockIdx.x * 256 + threadIdx.x;
    if (i < n4) {
        float4 v = reinterpret_cast<const float4*>(in)[i];
        uint2 o;
        o.x = h2u(v.x, v.y);
        o.y = h2u(v.z, v.w);
        reinterpret_cast<uint2*>(out)[i] = o;
    }
}

// ===========================================================================
// shared projection body: O[b][m][n] = sum_c W[m][c] X[b][c][n] + bias[m]
// ===========================================================================
__device__ __forceinline__ void proj_body(int which, int m0,
                                          const float* bq, const float* bk,
                                          const float* bv) {
    extern __shared__ __align__(16) char smem[];
    const uint32_t sb = smem_u32(smem);
    const int t = threadIdx.x, lane = t & 31, warp = t >> 5;
    const int wm = warp >> 1, wn = warp & 1;
    const int b = blockIdx.z, n0 = blockIdx.x * 128;

    const __half* W = (which == 0) ? g_Wqh : (which == 1) ? g_Wkh
                    : (which == 2) ? g_Wvh : g_Wph;
    const __half* X = (which <= 1) ? g_Xh : g_Yh;
    const float* bias = (which == 0) ? bq : (which == 1) ? bk : (which == 2) ? bv : nullptr;

    const __half* Wt = W + (size_t)m0 * Cc;
    const __half* Xb = X + (size_t)b * Cc * Nn + n0;

    const int grp = lane >> 3, lrow = lane & 7;
    const int gk8 = (grp & 2) ? 8 : 0, gm8 = (grp & 1) ? 8 : 0;
    const int agk16 = (grp & 2) ? 16 : 0, agm8 = (grp & 1) ? 8 : 0;
    int rowA[2], chB[4];
#pragma unroll
    for (int blk = 0; blk < 2; blk++) rowA[blk] = wm * 32 + blk * 16 + agm8 + lrow;
#pragma unroll
    for (int nb = 0; nb < 4; nb++) chB[nb] = (wn * 64 + nb * 16 + gm8) >> 3;

    const int STG = 34816;
#define PJ_A(s) (sb + (s) * STG)
#define PJ_B(s) (sb + (s) * STG + PAD_SZ)

    float acc[2][8][4];
#pragma unroll
    for (int i = 0; i < 2; i++)
#pragma unroll
        for (int j = 0; j < 8; j++)
#pragma unroll
            for (int e = 0; e < 4; e++) acc[i][j][e] = 0.f;

    const int KT = Cc / 64;  // 4
#pragma unroll
    for (int s = 0; s < 2; s++) {
        stage_mk(PJ_A(s), Wt + s * 64, Cc, t);
        stage_kn(PJ_B(s), Xb + (size_t)s * 64 * Nn, Nn, t);
        CP_COMMIT();
    }

    for (int kt = 0; kt < KT; kt++) {
        CP_WAIT1();
        __syncthreads();
        if (kt + 2 < KT) {
            const int sbuf = (kt + 2) % 3;
            stage_mk(PJ_A(sbuf), Wt + (kt + 2) * 64, Cc, t);
            stage_kn(PJ_B(sbuf), Xb + (size_t)(kt + 2) * 64 * Nn, Nn, t);
        }
        CP_COMMIT();
        const uint32_t sA = PJ_A(kt % 3), sB = PJ_B(kt % 3);
#pragma unroll
        for (int s = 0; s < 4; s++) {
            unsigned a[2][4];
            ldm4(a[0], sA + rowA[0] * 144 + s * 32 + agk16);
            ldm4(a[1], sA + rowA[1] * 144 + s * 32 + agk16);
            const int krow = s * 16 + gk8 + lrow;
#pragma unroll
            for (int nb = 0; nb < 4; nb++) {
                unsigned Bx[4];
                ldm4t(Bx, sB + krow * 256 + ((chB[nb] ^ lrow) << 4));
                unsigned b0[2] = { Bx[0], Bx[2] }, b1[2] = { Bx[1], Bx[3] };
                mma16(acc[0][2 * nb],     a[0], b0);
                mma16(acc[0][2 * nb + 1], a[0], b1);
                mma16(acc[1][2 * nb],     a[1], b0);
                mma16(acc[1][2 * nb + 1], a[1], b1);
            }
        }
    }

    const int g = lane >> 2, q = lane & 3;
    if (which <= 2) {
        __half* O = (which == 0) ? g_Qh : (which == 1) ? g_Kh : g_Vh;
#pragma unroll
        for (int fm = 0; fm < 2; fm++) {
            const int m = m0 + wm * 32 + fm * 16 + g;
            const float b0 = bias[m], b1 = bias[m + 8];
#pragma unroll
            for (int fn = 0; fn < 8; fn++) {
                const int n = n0 + wn * 64 + fn * 8 + 2 * q;
                *reinterpret_cast<__half2*>(&O[((size_t)b * HD + m) * Nn + n]) =
                    __floats2half2_rn(acc[fm][fn][0] + b0, acc[fm][fn][1] + b0);
                *reinterpret_cast<__half2*>(&O[((size_t)b * HD + m + 8) * Nn + n]) =
                    __floats2half2_rn(acc[fm][fn][2] + b1, acc[fm][fn][3] + b1);
            }
        }
    } else {
#pragma unroll
        for (int fm = 0; fm < 2; fm++) {
            const int m = m0 + wm * 32 + fm * 16 + g;
#pragma unroll
            for (int fn = 0; fn < 8; fn++) {
                const int n = n0 + wn * 64 + fn * 8 + 2 * q;
                *reinterpret_cast<float2*>(&g_YP[((size_t)b * Cc + m) * Nn + n]) =
                    make_float2(acc[fm][fn][0], acc[fm][fn][1]);
                *reinterpret_cast<float2*>(&g_YP[((size_t)b * Cc + m + 8) * Nn + n]) =
                    make_float2(acc[fm][fn][2], acc[fm][fn][3]);
            }
        }
    }
}

// proj for Q,K: blockIdx.y in [0,32): which=y>>4, m0=(y&15)*128
__global__ void __launch_bounds__(256, 2) proj_qk(const float* __restrict__ bq,
                                                  const float* __restrict__ bk) {
    proj_body(blockIdx.y >> 4, (blockIdx.y & 15) * 128, bq, bk, nullptr);
}
// proj for V,YP: blockIdx.y in [0,18): y<16 -> which=2,m0=y*128; else which=3,m0=(y-16)*128
__global__ void __launch_bounds__(256, 2) proj_vp(const float* __restrict__ bv) {
    int which, m0;
    if (blockIdx.y < 16) { which = 2; m0 = blockIdx.y * 128; }
    else                 { which = 3; m0 = (blockIdx.y - 16) * 128; }
    proj_body(which, m0, nullptr, nullptr, bv);
}

// ===========================================================================
// qk: P'[bh][i][j] = exp(sum_d Q[d][i] K[d][j] - C), plus per-CTA row sums.
// ===========================================================================
__global__ void __launch_bounds__(256, 2) qk_cp() {
    extern __shared__ __align__(16) char smem[];
    __shared__ float rs[128];
    const uint32_t sb = smem_u32(smem);
    const int t = threadIdx.x, lane = t & 31, warp = t >> 5;
    const int wm = warp >> 1, wn = warp & 1;
    const int bh = blockIdx.z, i0 = blockIdx.y * 128, j0 = blockIdx.x * 128;

    const __half* Q = g_Qh + (size_t)bh * Dd * Nn + i0;
    const __half* K = g_Kh + (size_t)bh * Dd * Nn + j0;

    const int grp = lane >> 3, lrow = lane & 7;
    const int gk8 = (grp & 2) ? 8 : 0, gm8 = (grp & 1) ? 8 : 0;
    int chA[2], chB[4];
#pragma unroll
    for (int blk = 0; blk < 2; blk++) chA[blk] = (wm * 32 + blk * 16 + gm8) >> 3;
#pragma unroll
    for (int nb = 0; nb < 4; nb++) chB[nb] = (wn * 64 + nb * 16 + gm8) >> 3;

    if (t < 128) rs[t] = 0.f;

    const int STG = 32768;
#define QK_A(s) (sb + (s) * STG)
#define QK_B(s) (sb + (s) * STG + SWZ_SZ)

    float acc[2][8][4];
#pragma unroll
    for (int i = 0; i < 2; i++)
#pragma unroll
        for (int j = 0; j < 8; j++)
#pragma unroll
            for (int e = 0; e < 4; e++) acc[i][j][e] = 0.f;

    const int KT = Dd / 64;  // 4
#pragma unroll
    for (int s = 0; s < 2; s++) {
        stage_kn(QK_A(s), Q + (size_t)s * 64 * Nn, Nn, t);
        stage_kn(QK_B(s), K + (size_t)s * 64 * Nn, Nn, t);
        CP_COMMIT();
    }

    for (int kt = 0; kt < KT; kt++) {
        CP_WAIT1();
        __syncthreads();
        if (kt + 2 < KT) {
            const int sbuf = (kt + 2) % 3;
            stage_kn(QK_A(sbuf), Q + (size_t)(kt + 2) * 64 * Nn, Nn, t);
            stage_kn(QK_B(sbuf), K + (size_t)(kt + 2) * 64 * Nn, Nn, t);
        }
        CP_COMMIT();
        const uint32_t sA = QK_A(kt % 3), sB = QK_B(kt % 3);
#pragma unroll
        for (int s = 0; s < 4; s++) {
            const int krow = s * 16 + gk8 + lrow;
            unsigned a[2][4];
            ldm4t(a[0], sA + krow * 256 + ((chA[0] ^ lrow) << 4));
            ldm4t(a[1], sA + krow * 256 + ((chA[1] ^ lrow) << 4));
#pragma unroll
            for (int nb = 0; nb < 4; nb++) {
                unsigned Bx[4];
                ldm4t(Bx, sB + krow * 256 + ((chB[nb] ^ lrow) << 4));
                unsigned b0[2] = { Bx[0], Bx[2] }, b1[2] = { Bx[1], Bx[3] };
                mma16(acc[0][2 * nb],     a[0], b0);
                mma16(acc[0][2 * nb + 1], a[0], b1);
                mma16(acc[1][2 * nb],     a[1], b0);
                mma16(acc[1][2 * nb + 1], a[1], b1);
            }
        }
    }

    // Epilogue: p' = exp(s - C) -> fp16 store; row partial sums (fp16-rounded).
    __half* S = g_Sh + (size_t)bh * Nn * Nn;
    const int g = lane >> 2, q = lane & 3;
#pragma unroll
    for (int fm = 0; fm < 2; fm++) {
        const int lr0 = wm * 32 + fm * 16 + g;
        const int r = i0 + lr0;
        float s0 = 0.f, s1 = 0.f;
#pragma unroll
        for (int fn = 0; fn < 8; fn++) {
            const int c = j0 + wn * 64 + fn * 8 + 2 * q;
            float e00 = __expf(acc[fm][fn][0] - CEXP);
            float e01 = __expf(acc[fm][fn][1] - CEXP);
            float e10 = __expf(acc[fm][fn][2] - CEXP);
            float e11 = __expf(acc[fm][fn][3] - CEXP);
            __half2 h0 = __floats2half2_rn(e00, e01);
            __half2 h1 = __floats2half2_rn(e10, e11);
            *reinterpret_cast<__half2*>(&S[(size_t)r * Nn + c]) = h0;
            *reinterpret_cast<__half2*>(&S[(size_t)(r + 8) * Nn + c]) = h1;
            float2 f0 = __half22float2(h0), f1 = __half22float2(h1);
            s0 += f0.x + f0.y;
            s1 += f1.x + f1.y;
        }
        s0 += __shfl_xor_sync(0xffffffffu, s0, 1);
        s0 += __shfl_xor_sync(0xffffffffu, s0, 2);
        s1 += __shfl_xor_sync(0xffffffffu, s1, 1);
        s1 += __shfl_xor_sync(0xffffffffu, s1, 2);
        if (q == 0) {
            atomicAdd(&rs[lr0], s0);       // 2 adds/row: commutative, deterministic
            atomicAdd(&rs[lr0 + 8], s1);
        }
    }
    __syncthreads();
    if (t < 128)
        g_Lp[((size_t)bh * Nn + i0 + t) * 8 + blockIdx.x] = rs[t];
}

// ===========================================================================
// av: out = (gamma * (V P'^T) * il[i] + yp)/(1+gamma). CTA 128(d) x 128(i).
// Row-sum inverse computed in prologue from g_Lp (sum_l kernel folded in).
// ===========================================================================
__global__ void __launch_bounds__(256, 2) av_cp(const float* __restrict__ gamma,
                                                float* __restrict__ out) {
    extern __shared__ __align__(16) char smem[];
    __shared__ float sIL[128];
    const uint32_t sb = smem_u32(smem);
    const int t = threadIdx.x, lane = t & 31, warp = t >> 5;
    const int wm = warp >> 1, wn = warp & 1;
    const int bh = blockIdx.z, b = bh >> 3, h = bh & 7;
    const int d0 = blockIdx.y * 128, i0 = blockIdx.x * 128;

    const __half* V = g_Vh + ((size_t)bh * Dd + d0) * Nn;
    const __half* P = g_Sh + ((size_t)bh * Nn + i0) * Nn;

    if (t < 128) {
        const float4* lp = reinterpret_cast<const float4*>(
            g_Lp + ((size_t)bh * Nn + i0 + t) * 8);
        float4 a4 = lp[0], b4 = lp[1];
        sIL[t] = 1.f / (((a4.x + a4.y) + (a4.z + a4.w)) + ((b4.x + b4.y) + (b4.z + b4.w)));
    }

    const int grp = lane >> 3, lrow = lane & 7;
    const int gk16 = (grp & 2) ? 16 : 0, gm8 = (grp & 1) ? 8 : 0;
    const int bk16 = (grp & 1) ? 16 : 0, bn8 = (grp & 2) ? 8 : 0;
    int rowA[2], rowB[4];
#pragma unroll
    for (int blk = 0; blk < 2; blk++) rowA[blk] = wm * 32 + blk * 16 + gm8 + lrow;
#pragma unroll
    for (int nb = 0; nb < 4; nb++) rowB[nb] = wn * 64 + nb * 16 + bn8 + lrow;

    const int STG = 36864;
#define AV_A(s) (sb + (s) * STG)
#define AV_B(s) (sb + (s) * STG + PAD_SZ)

    float acc[2][8][4];
#pragma unroll
    for (int i = 0; i < 2; i++)
#pragma unroll
        for (int j = 0; j < 8; j++)
#pragma unroll
            for (int e = 0; e < 4; e++) acc[i][j][e] = 0.f;

    const int KT = Nn / 64;  // 16
#pragma unroll
    for (int s = 0; s < 2; s++) {
        stage_mk(AV_A(s), V + s * 64, Nn, t);
        stage_mk(AV_B(s), P + s * 64, Nn, t);
        CP_COMMIT();
    }

    for (int kt = 0; kt < KT; kt++) {
        CP_WAIT1();
        __syncthreads();
        if (kt + 2 < KT) {
            const int sbuf = (kt + 2) % 3;
            stage_mk(AV_A(sbuf), V + (kt + 2) * 64, Nn, t);
            stage_mk(AV_B(sbuf), P + (kt + 2) * 64, Nn, t);
        }
        CP_COMMIT();
        const uint32_t sA = AV_A(kt % 3), sB = AV_B(kt % 3);
#pragma unroll
        for (int s = 0; s < 4; s++) {
            unsigned a[2][4];
            ldm4(a[0], sA + rowA[0] * 144 + s * 32 + gk16);
            ldm4(a[1], sA + rowA[1] * 144 + s * 32 + gk16);
#pragma unroll
            for (int nb = 0; nb < 4; nb++) {
                unsigned Bx[4];
                ldm4(Bx, sB + rowB[nb] * 144 + s * 32 + bk16);
                unsigned b0[2] = { Bx[0], Bx[1] }, b1[2] = { Bx[2], Bx[3] };
                mma16(acc[0][2 * nb],     a[0], b0);
                mma16(acc[0][2 * nb + 1], a[0], b1);
                mma16(acc[1][2 * nb],     a[1], b0);
                mma16(acc[1][2 * nb + 1], a[1], b1);
            }
        }
    }

    const float gm = gamma[h], inv = 1.f / (1.f + gm);
    const int g = lane >> 2, q = lane & 3;

    float ilx[8], ily[8];
#pragma unroll
    for (int fn = 0; fn < 8; fn++) {
        const int il = wn * 64 + fn * 8 + 2 * q;
        ilx[fn] = sIL[il];
        ily[fn] = sIL[il + 1];
    }

#pragma unroll
    for (int fm = 0; fm < 2; fm++) {
        const int d = d0 + wm * 32 + fm * 16 + g;
#pragma unroll
        for (int fn = 0; fn < 8; fn++) {
            const int i = i0 + wn * 64 + fn * 8 + 2 * q;
            const float2 yp0 = *reinterpret_cast<const float2*>(
                &g_YP[((size_t)b * Cc + d) * Nn + i]);
            const float2 yp1 = *reinterpret_cast<const float2*>(
                &g_YP[((size_t)b * Cc + d + 8) * Nn + i]);
            float* p0 = out + ((size_t)b * HD + (size_t)h * Dd + d) * Nn + i;
            float* p1 = out + ((size_t)b * HD + (size_t)h * Dd + d + 8) * Nn + i;
            *reinterpret_cast<float2*>(p0) =
                make_float2((gm * acc[fm][fn][0] * ilx[fn] + yp0.x) * inv,
                            (gm * acc[fm][fn][1] * ily[fn] + yp0.y) * inv);
            *reinterpret_cast<float2*>(p1) =
                make_float2((gm * acc[fm][fn][2] * ilx[fn] + yp1.x) * inv,
                            (gm * acc[fm][fn][3] * ily[fn] + yp1.y) * inv);
        }
    }
}

// ---------------------------------------------------------------------------
extern "C" void kernel_launch(void* const* d_in, const int* in_sizes, int n_in,
                              void* d_out, int out_size) {
    const float* x     = (const float*)d_in[0];
    const float* y     = (const float*)d_in[1];
    const float* Wq    = (const float*)d_in[2];
    const float* bq    = (const float*)d_in[3];
    const float* Wk    = (const float*)d_in[4];
    const float* bk    = (const float*)d_in[5];
    const float* Wv    = (const float*)d_in[6];
    const float* bv    = (const float*)d_in[7];
    const float* Wp    = (const float*)d_in[8];
    const float* gamma = (const float*)d_in[9];
    float* out = (float*)d_out;

    static bool init_done = false;
    static cudaStream_t s1;
    static cudaEvent_t evFork, evJoin;
    if (!init_done) {
        cudaFuncSetAttribute(qk_cp,   cudaFuncAttributeMaxDynamicSharedMemorySize, 3 * 32768);
        cudaFuncSetAttribute(av_cp,   cudaFuncAttributeMaxDynamicSharedMemorySize, 3 * 36864);
        cudaFuncSetAttribute(proj_qk, cudaFuncAttributeMaxDynamicSharedMemorySize, 3 * 34816);
        cudaFuncSetAttribute(proj_vp, cudaFuncAttributeMaxDynamicSharedMemorySize, 3 * 34816);
        cudaStreamCreateWithFlags(&s1, cudaStreamNonBlocking);
        cudaEventCreateWithFlags(&evFork, cudaEventDisableTiming);
        cudaEventCreateWithFlags(&evJoin, cudaEventDisableTiming);
        init_done = true;
    }

    dim3 blk(256);

    // Fork side stream
    cudaEventRecord(evFork, 0);
    cudaStreamWaitEvent(s1, evFork, 0);

    // Stream 0 chain: f2h{x,Wq,Wk} -> proj{Q,K} -> qk
    f2h_grp<<<dim3(1024, 3), blk>>>(x, Wq, Wk, 0);
    proj_qk<<<dim3(Nn / 128, 32, Bn), blk, 3 * 34816>>>(bq, bk);
    qk_cp<<<dim3(Nn / 128, Nn / 128, Bn * Hh), blk, 3 * 32768>>>();

    // Side stream: f2h{y,Wv,Wp} -> proj{V,YP}   (needed only by av)
    f2h_grp<<<dim3(1024, 3), blk, 0, s1>>>(y, Wv, Wp, 1);
    proj_vp<<<dim3(Nn / 128, 18, Bn), blk, 3 * 34816, s1>>>(bv);
    cudaEventRecord(evJoin, s1);

    // Join, then av (sum_l folded into its prologue)
    cudaStreamWaitEvent(0, evJoin, 0);
    av_cp<<<dim3(Nn / 128, Dd / 128, Bn * Hh), blk, 3 * 36864>>>(gamma, out);
}